// round 1
// baseline (speedup 1.0000x reference)
#include <cuda_runtime.h>

#define NN   100000
#define EE   1600000
#define GG   100
#define DIN  3
#define HH   128
#define OUTF 10
#define CAP  128   // max in-degree supported (Poisson mean 16; P(deg>=128) ~ 0)

// ---------- device scratch (no allocations allowed) ----------
__device__ float g_bufA[(size_t)NN * HH];   // 51.2 MB
__device__ float g_bufB[(size_t)NN * HH];   // 51.2 MB
__device__ int   g_pad[(size_t)NN * CAP];   // padded incoming adjacency (src ids)
__device__ int   g_cnt[NN];                 // in-degree (excl self loop)
__device__ int   g_cur[NN];                 // fill cursor
__device__ float g_dis[NN];                 // deg^-1/2 (deg incl self loop)
__device__ float g_di[NN];                  // deg^-1
__device__ float g_pooled[GG * HH];
__device__ float g_gcnt[GG];

// ---------- kernels ----------
__global__ void k_zero() {
    int i = blockIdx.x * blockDim.x + threadIdx.x;
    if (i < NN) { g_cnt[i] = 0; g_cur[i] = 0; }
    if (i < GG * HH) g_pooled[i] = 0.f;
    if (i < GG) g_gcnt[i] = 0.f;
}

__global__ void k_count(const int* __restrict__ dst) {
    int e = blockIdx.x * blockDim.x + threadIdx.x;
    if (e < EE) atomicAdd(&g_cnt[dst[e]], 1);
}

__global__ void k_deg() {
    int i = blockIdx.x * blockDim.x + threadIdx.x;
    if (i < NN) {
        float d = (float)(g_cnt[i] + 1);   // +1 self loop
        g_dis[i] = rsqrtf(d);
        g_di[i]  = 1.f / d;
    }
}

__global__ void k_fill(const int* __restrict__ src, const int* __restrict__ dst) {
    int e = blockIdx.x * blockDim.x + threadIdx.x;
    if (e < EE) {
        int d = dst[e];
        int p = atomicAdd(&g_cur[d], 1);
        if (p < CAP) g_pad[(size_t)d * CAP + p] = src[e];
    }
}

// h = x @ W1  (N x 3 @ 3 x 128), warp per node, float4 per lane
__global__ void k_gemm_in(const float* __restrict__ x, const float* __restrict__ W1,
                          float* __restrict__ hout) {
    int gid = blockIdx.x * blockDim.x + threadIdx.x;
    int n = gid >> 5, lane = gid & 31;
    if (n >= NN) return;
    float x0 = x[n * 3 + 0], x1 = x[n * 3 + 1], x2 = x[n * 3 + 2];
    const float4* W = ((const float4*)W1) + lane;   // row stride = 32 float4
    float4 w0 = W[0], w1 = W[32], w2 = W[64];
    float4 o;
    o.x = fmaf(x0, w0.x, fmaf(x1, w1.x, x2 * w2.x));
    o.y = fmaf(x0, w0.y, fmaf(x1, w1.y, x2 * w2.y));
    o.z = fmaf(x0, w0.z, fmaf(x1, w1.z, x2 * w2.z));
    o.w = fmaf(x0, w0.w, fmaf(x1, w1.w, x2 * w2.w));
    ((float4*)(hout + (size_t)n * HH))[lane] = o;
}

// out_i = relu( d_i^-1/2 * sum_j d_j^-1/2 h_j  +  d_i^-1 h_i  +  b )
// warp per destination node; register accumulator (float4/lane)
__global__ void k_agg(const float* __restrict__ hin, float* __restrict__ hout,
                      const float* __restrict__ bias) {
    int gid = blockIdx.x * blockDim.x + threadIdx.x;
    int n = gid >> 5, lane = gid & 31;
    if (n >= NN) return;
    int cnt = g_cnt[n]; if (cnt > CAP) cnt = CAP;
    const int* lst = g_pad + (size_t)n * CAP;
    float ax = 0.f, ay = 0.f, az = 0.f, aw = 0.f;
    for (int k = 0; k < cnt; k++) {
        int s = __ldg(&lst[k]);                       // uniform broadcast load
        float w = g_dis[s];
        float4 v = ((const float4*)(hin + (size_t)s * HH))[lane];
        ax = fmaf(w, v.x, ax);
        ay = fmaf(w, v.y, ay);
        az = fmaf(w, v.z, az);
        aw = fmaf(w, v.w, aw);
    }
    float ds = g_dis[n], di = g_di[n];
    float4 hv = ((const float4*)(hin + (size_t)n * HH))[lane];
    float4 b  = ((const float4*)bias)[lane];
    float4 o;
    o.x = fmaxf(fmaf(ax, ds, fmaf(hv.x, di, b.x)), 0.f);
    o.y = fmaxf(fmaf(ay, ds, fmaf(hv.y, di, b.y)), 0.f);
    o.z = fmaxf(fmaf(az, ds, fmaf(hv.z, di, b.z)), 0.f);
    o.w = fmaxf(fmaf(aw, ds, fmaf(hv.w, di, b.w)), 0.f);
    ((float4*)(hout + (size_t)n * HH))[lane] = o;
}

// hout = hin @ W2  (N x 128 @ 128 x 128), warp per node, W2 rows from L1
__global__ void k_gemm_h(const float* __restrict__ hin, float* __restrict__ hout,
                         const float* __restrict__ W2) {
    int gid = blockIdx.x * blockDim.x + threadIdx.x;
    int n = gid >> 5, lane = gid & 31;
    if (n >= NN) return;
    const float4* row4 = (const float4*)(hin + (size_t)n * HH);
    const float4* Wb = ((const float4*)W2) + lane;    // row stride = 32 float4
    float ax = 0.f, ay = 0.f, az = 0.f, aw = 0.f;
#pragma unroll 4
    for (int k4 = 0; k4 < 32; k4++) {
        float4 hv = row4[k4];                         // broadcast, L1-resident
        const float4* w = Wb + (size_t)k4 * 128;      // 4 consecutive rows
        float4 w0 = w[0], w1 = w[32], w2 = w[64], w3 = w[96];
        ax = fmaf(hv.x, w0.x, fmaf(hv.y, w1.x, fmaf(hv.z, w2.x, fmaf(hv.w, w3.x, ax))));
        ay = fmaf(hv.x, w0.y, fmaf(hv.y, w1.y, fmaf(hv.z, w2.y, fmaf(hv.w, w3.y, ay))));
        az = fmaf(hv.x, w0.z, fmaf(hv.y, w1.z, fmaf(hv.z, w2.z, fmaf(hv.w, w3.z, az))));
        aw = fmaf(hv.x, w0.w, fmaf(hv.y, w1.w, fmaf(hv.z, w2.w, fmaf(hv.w, w3.w, aw))));
    }
    float4 o; o.x = ax; o.y = ay; o.z = az; o.w = aw;
    ((float4*)(hout + (size_t)n * HH))[lane] = o;
}

__global__ void k_pool(const float* __restrict__ hin, const int* __restrict__ batch) {
    int idx = blockIdx.x * blockDim.x + threadIdx.x;
    if (idx >= NN * HH) return;
    int n = idx >> 7, f = idx & 127;
    int g = batch[n];
    atomicAdd(&g_pooled[g * HH + f], hin[idx]);
    if (f == 0) atomicAdd(&g_gcnt[g], 1.f);
}

__global__ void k_final(const float* __restrict__ Wl, const float* __restrict__ bl,
                        float* __restrict__ out) {
    int idx = blockIdx.x * blockDim.x + threadIdx.x;
    if (idx >= GG * OUTF) return;
    int g = idx / OUTF, o = idx % OUTF;
    float inv = 1.f / fmaxf(g_gcnt[g], 1.f);
    float s = 0.f;
#pragma unroll 8
    for (int k = 0; k < HH; k++)
        s = fmaf(g_pooled[g * HH + k], Wl[k * OUTF + o], s);
    out[idx] = fmaf(s, inv, bl[o]);
}

// ---------- launch ----------
extern "C" void kernel_launch(void* const* d_in, const int* in_sizes, int n_in,
                              void* d_out, int out_size) {
    const float* x     = (const float*)d_in[0];
    const int*   ei    = (const int*)d_in[1];
    const int*   src   = ei;
    const int*   dst   = ei + EE;
    const int*   batch = (const int*)d_in[2];
    const float* W1    = (const float*)d_in[3];
    const float* b1    = (const float*)d_in[4];
    const float* W2    = (const float*)d_in[5];
    const float* b2    = (const float*)d_in[6];
    const float* Wl    = (const float*)d_in[7];
    const float* bl    = (const float*)d_in[8];
    float* out = (float*)d_out;

    float *bufA, *bufB;
    cudaGetSymbolAddress((void**)&bufA, g_bufA);
    cudaGetSymbolAddress((void**)&bufB, g_bufB);

    const int T = 256;
    int bN  = (NN + T - 1) / T;            // 391
    int bE  = (EE + T - 1) / T;            // 6250
    int bW  = (NN * 32 + T - 1) / T;       // 12500  (warp per node)
    int bP  = (NN * HH + T - 1) / T;       // 50000
    int bF  = (GG * OUTF + T - 1) / T;     // 4

    k_zero<<<bN, T>>>();
    k_count<<<bE, T>>>(dst);
    k_deg<<<bN, T>>>();
    k_fill<<<bE, T>>>(src, dst);

    // layer 1
    k_gemm_in<<<bW, T>>>(x, W1, bufA);
    k_agg<<<bW, T>>>(bufA, bufB, b1);
    // layer 2
    k_gemm_h<<<bW, T>>>(bufB, bufA, W2);
    k_agg<<<bW, T>>>(bufA, bufB, b2);
    // pooling + head
    k_pool<<<bP, T>>>(bufB, batch);
    k_final<<<bF, T>>>(Wl, bl, out);
}